// round 6
// baseline (speedup 1.0000x reference)
#include <cuda_runtime.h>
#include <cstdint>

#define N_NODES 50000
#define DFEAT 128
#define MAX_E 800000
#define GEMM_ROWS 64
#define GEMM_SMEM ((DFEAT*DFEAT + GEMM_ROWS*DFEAT) * 4)  // 64KB W + 32KB X tile

// ---- scratch (static device globals: allocation-free) ----
__device__ float g_hs[N_NODES * DFEAT];    // (X@W) * dinv[row]
__device__ float g_buf[N_NODES * DFEAT];   // layer-1 output / layer-2 input
__device__ float g_dinv[N_NODES];
__device__ int   g_cnt[N_NODES];           // after scan: rowptr start
__device__ int   g_cursor[N_NODES];        // fill cursor; after fill: rowptr end
__device__ int   g_csr[MAX_E];

// ---------------- graph build ----------------
__global__ void zero_counters() {
    int i = blockIdx.x * blockDim.x + threadIdx.x;
    if (i < N_NODES) g_cnt[i] = 0;
}

// 4 edges per thread, int4 loads -> MLP 4 on the atomic chains
__global__ void count_deg4(const int4* __restrict__ dst4, int n4) {
    int t = blockIdx.x * blockDim.x + threadIdx.x;
    if (t < n4) {
        int4 d = dst4[t];
        atomicAdd(&g_cnt[d.x], 1);
        atomicAdd(&g_cnt[d.y], 1);
        atomicAdd(&g_cnt[d.z], 1);
        atomicAdd(&g_cnt[d.w], 1);
    }
}

__global__ void count_deg(const int* __restrict__ dst, int E) {
    int e = blockIdx.x * blockDim.x + threadIdx.x;
    if (e < E) atomicAdd(&g_cnt[dst[e]], 1);
}

// single-block scan over 50000 counts; seeds cursor=rowptr, dinv=rsqrt(deg+1)
__global__ void scan_deg() {
    __shared__ int part[1024];
    int t = threadIdx.x;
    const int C = (N_NODES + 1023) / 1024;   // 49
    int lo = t * C;
    int hi = min(lo + C, N_NODES);
    int s = 0;
    for (int i = lo; i < hi; i++) s += g_cnt[i];
    part[t] = s;
    __syncthreads();
    for (int off = 1; off < 1024; off <<= 1) {
        int v = (t >= off) ? part[t - off] : 0;
        __syncthreads();
        part[t] += v;
        __syncthreads();
    }
    int run = (t > 0) ? part[t - 1] : 0;
    for (int i = lo; i < hi; i++) {
        g_cursor[i] = run;                   // absolute fill cursor
        int c = g_cnt[i];
        g_cnt[i] = run;                      // rowptr start (reuse cnt)
        run += c;
        g_dinv[i] = rsqrtf((float)c + 1.0f);
    }
}

__global__ void fill_csr4(const int4* __restrict__ src4,
                          const int4* __restrict__ dst4, int n4) {
    int t = blockIdx.x * blockDim.x + threadIdx.x;
    if (t < n4) {
        int4 s = src4[t];
        int4 d = dst4[t];
        int p0 = atomicAdd(&g_cursor[d.x], 1);
        int p1 = atomicAdd(&g_cursor[d.y], 1);
        int p2 = atomicAdd(&g_cursor[d.z], 1);
        int p3 = atomicAdd(&g_cursor[d.w], 1);
        g_csr[p0] = s.x;
        g_csr[p1] = s.y;
        g_csr[p2] = s.z;
        g_csr[p3] = s.w;
    }
}

__global__ void fill_csr(const int* __restrict__ src,
                         const int* __restrict__ dst, int E) {
    int e = blockIdx.x * blockDim.x + threadIdx.x;
    if (e < E) {
        int pos = atomicAdd(&g_cursor[dst[e]], 1);
        g_csr[pos] = src[e];
    }
}

// ---------------- GEMM: out[row] = (X[row] @ W) * dinv[row] (round-2 scalar) --------
// block = 256 threads, 64 rows per block, full 128x128 W in smem.
// warp w handles rows w*8 .. w*8+7; lane handles 4 columns (float4).
__global__ void gemm_scale(const float* __restrict__ X, const float* __restrict__ W,
                           float* __restrict__ out, int nrows) {
    extern __shared__ float sm[];
    float* Ws = sm;                       // 128*128
    float* Xs = sm + DFEAT * DFEAT;       // 64*128
    int tid = threadIdx.x;

    float4* Ws4 = (float4*)Ws;
    const float4* W4 = (const float4*)W;
    for (int i = tid; i < DFEAT * DFEAT / 4; i += 256) Ws4[i] = W4[i];

    int row0 = blockIdx.x * GEMM_ROWS;
    int nr = min(GEMM_ROWS, nrows - row0);
    float4* Xs4 = (float4*)Xs;
    const float4* X4 = (const float4*)(X + (size_t)row0 * DFEAT);
    for (int i = tid; i < nr * 32; i += 256) Xs4[i] = X4[i];
    for (int i = nr * 32 + tid; i < GEMM_ROWS * 32; i += 256)
        Xs4[i] = make_float4(0.f, 0.f, 0.f, 0.f);
    __syncthreads();

    int warp = tid >> 5, lane = tid & 31;
    float4 acc[8];
#pragma unroll
    for (int r = 0; r < 8; r++) acc[r] = make_float4(0.f, 0.f, 0.f, 0.f);

    for (int k = 0; k < DFEAT; k++) {
        float4 w4 = Ws4[k * 32 + lane];
#pragma unroll
        for (int r = 0; r < 8; r++) {
            float xv = Xs[(warp * 8 + r) * DFEAT + k];   // broadcast within warp
            acc[r].x = fmaf(xv, w4.x, acc[r].x);
            acc[r].y = fmaf(xv, w4.y, acc[r].y);
            acc[r].z = fmaf(xv, w4.z, acc[r].z);
            acc[r].w = fmaf(xv, w4.w, acc[r].w);
        }
    }

#pragma unroll
    for (int r = 0; r < 8; r++) {
        int row = warp * 8 + r;
        if (row < nr) {
            float dsc = g_dinv[row0 + row];
            float4 v;
            v.x = acc[r].x * dsc; v.y = acc[r].y * dsc;
            v.z = acc[r].z * dsc; v.w = acc[r].w * dsc;
            ((float4*)out)[(size_t)(row0 + row) * 32 + lane] = v;
        }
    }
}

// ------ aggregation: out = relu(dinv[n]*(hs[n] + sum hs[s]) + b), hs pre-scaled ------
__global__ void aggregate_relu(const float* __restrict__ hs,
                               const float* __restrict__ bias,
                               float* __restrict__ out) {
    int gw = (blockIdx.x * blockDim.x + threadIdx.x) >> 5;
    int lane = threadIdx.x & 31;
    if (gw >= N_NODES) return;
    const float4* hs4 = (const float4*)hs;
    float4 acc = hs4[(size_t)gw * 32 + lane];   // self term (already dinv[n]-scaled)
    int e0 = g_cnt[gw];
    int e1 = g_cursor[gw];
#pragma unroll 4
    for (int e = e0; e < e1; e++) {
        int s = g_csr[e];                        // broadcast load
        float4 v = hs4[(size_t)s * 32 + lane];
        acc.x += v.x; acc.y += v.y; acc.z += v.z; acc.w += v.w;
    }
    float d = g_dinv[gw];
    float4 b = ((const float4*)bias)[lane];
    float4 r;
    r.x = fmaxf(fmaf(acc.x, d, b.x), 0.f);
    r.y = fmaxf(fmaf(acc.y, d, b.y), 0.f);
    r.z = fmaxf(fmaf(acc.z, d, b.z), 0.f);
    r.w = fmaxf(fmaf(acc.w, d, b.w), 0.f);
    ((float4*)out)[(size_t)gw * 32 + lane] = r;
}

// layer-2 aggregation fused with final 128->1 projection
__global__ void aggregate_final(const float* __restrict__ hs,
                                const float* __restrict__ bias,
                                const float* __restrict__ Wl,
                                const float* __restrict__ bl,
                                float* __restrict__ out) {
    int gw = (blockIdx.x * blockDim.x + threadIdx.x) >> 5;
    int lane = threadIdx.x & 31;
    if (gw >= N_NODES) return;
    const float4* hs4 = (const float4*)hs;
    float4 acc = hs4[(size_t)gw * 32 + lane];
    int e0 = g_cnt[gw];
    int e1 = g_cursor[gw];
#pragma unroll 4
    for (int e = e0; e < e1; e++) {
        int s = g_csr[e];
        float4 v = hs4[(size_t)s * 32 + lane];
        acc.x += v.x; acc.y += v.y; acc.z += v.z; acc.w += v.w;
    }
    float d = g_dinv[gw];
    float4 b = ((const float4*)bias)[lane];
    float4 r;
    r.x = fmaxf(fmaf(acc.x, d, b.x), 0.f);
    r.y = fmaxf(fmaf(acc.y, d, b.y), 0.f);
    r.z = fmaxf(fmaf(acc.z, d, b.z), 0.f);
    r.w = fmaxf(fmaf(acc.w, d, b.w), 0.f);
    float4 wl = ((const float4*)Wl)[lane];
    float dot = r.x * wl.x + r.y * wl.y + r.z * wl.z + r.w * wl.w;
#pragma unroll
    for (int off = 16; off; off >>= 1)
        dot += __shfl_xor_sync(0xFFFFFFFFu, dot, off);
    if (lane == 0) out[gw] = dot + bl[0];
}

// ---------------- launch ----------------
extern "C" void kernel_launch(void* const* d_in, const int* in_sizes, int n_in,
                              void* d_out, int out_size) {
    const float* x  = (const float*)d_in[0];
    const int*   ei = (const int*)d_in[1];    // int32 (JAX x64 disabled)
    const float* W1 = (const float*)d_in[2];
    const float* b1 = (const float*)d_in[3];
    const float* W2 = (const float*)d_in[4];
    const float* b2 = (const float*)d_in[5];
    const float* Wl = (const float*)d_in[6];
    const float* bl = (const float*)d_in[7];
    float* out = (float*)d_out;

    int E = in_sizes[1] / 2;
    const int* src = ei;
    const int* dst = ei + E;

    void *p_hs, *p_buf;
    cudaGetSymbolAddress(&p_hs, g_hs);
    cudaGetSymbolAddress(&p_buf, g_buf);
    float* hs  = (float*)p_hs;
    float* buf = (float*)p_buf;

    static bool attr_ok = []() {
        cudaFuncSetAttribute(gemm_scale, cudaFuncAttributeMaxDynamicSharedMemorySize, GEMM_SMEM);
        return true;
    }();
    (void)attr_ok;

    int gemm_grid = (N_NODES + GEMM_ROWS - 1) / GEMM_ROWS;
    int agg_grid  = (N_NODES + 7) / 8;   // 8 warps / 256-thread block

    bool vec4 = ((E & 3) == 0) &&
                ((((uintptr_t)src) & 15) == 0) && ((((uintptr_t)dst) & 15) == 0);

    zero_counters<<<(N_NODES + 255) / 256, 256>>>();
    if (vec4) {
        int n4 = E / 4;
        count_deg4<<<(n4 + 255) / 256, 256>>>((const int4*)dst, n4);
        scan_deg<<<1, 1024>>>();
        fill_csr4<<<(n4 + 255) / 256, 256>>>((const int4*)src, (const int4*)dst, n4);
    } else {
        count_deg<<<(E + 255) / 256, 256>>>(dst, E);
        scan_deg<<<1, 1024>>>();
        fill_csr<<<(E + 255) / 256, 256>>>(src, dst, E);
    }

    gemm_scale<<<gemm_grid, 256, GEMM_SMEM>>>(x, W1, hs, N_NODES);
    aggregate_relu<<<agg_grid, 256>>>(hs, b1, buf);
    gemm_scale<<<gemm_grid, 256, GEMM_SMEM>>>(buf, W2, hs, N_NODES);
    aggregate_final<<<agg_grid, 256>>>(hs, b2, Wl, bl, out);
}

// round 9
// speedup vs baseline: 1.2230x; 1.2230x over previous
#include <cuda_runtime.h>
#include <cuda_bf16.h>
#include <cstdint>

#define N_NODES 50000
#define DFEAT 128
#define MAX_E 800000

// ---- scratch (static device globals: allocation-free) ----
__device__ float g_hs[N_NODES * DFEAT];    // (X@W) * dinv[row]
__device__ float g_buf[N_NODES * DFEAT];   // layer-1 output / layer-2 input
__device__ float g_dinv[N_NODES];
__device__ int   g_cnt[N_NODES];
__device__ int   g_cursor[N_NODES];
__device__ int   g_rowptr[N_NODES + 1];
__device__ int   g_csr[MAX_E];
__device__ __nv_bfloat16 g_wh[DFEAT * DFEAT];   // W^T hi  [n][k]
__device__ __nv_bfloat16 g_wl[DFEAT * DFEAT];   // W^T lo  [n][k]

// ---------------- graph build (round-2 verbatim) ----------------
__global__ void zero_counters() {
    int i = blockIdx.x * blockDim.x + threadIdx.x;
    if (i < N_NODES) { g_cnt[i] = 0; g_cursor[i] = 0; }
}
__global__ void count_deg(const int* __restrict__ dst, int E) {
    int e = blockIdx.x * blockDim.x + threadIdx.x;
    if (e < E) atomicAdd(&g_cnt[dst[e]], 1);
}
__global__ void scan_deg(int E) {
    __shared__ int part[1024];
    int t = threadIdx.x;
    const int C = (N_NODES + 1023) / 1024;
    int lo = t * C, hi = min(lo + C, N_NODES);
    int s = 0;
    for (int i = lo; i < hi; i++) s += g_cnt[i];
    part[t] = s;
    __syncthreads();
    for (int off = 1; off < 1024; off <<= 1) {
        int v = (t >= off) ? part[t - off] : 0;
        __syncthreads();
        part[t] += v;
        __syncthreads();
    }
    int run = (t > 0) ? part[t - 1] : 0;
    for (int i = lo; i < hi; i++) {
        g_rowptr[i] = run;
        int c = g_cnt[i];
        run += c;
        g_dinv[i] = rsqrtf((float)c + 1.0f);
    }
    if (t == 0) g_rowptr[N_NODES] = E;
}
__global__ void fill_csr(const int* __restrict__ src,
                         const int* __restrict__ dst, int E) {
    int e = blockIdx.x * blockDim.x + threadIdx.x;
    if (e < E) {
        int d = dst[e];
        int pos = atomicAdd(&g_cursor[d], 1);
        g_csr[g_rowptr[d] + pos] = src[e];
    }
}

// ---------------- W -> transposed bf16 hi/lo ----------------
__global__ void wconvert(const float* __restrict__ W) {
    int i = blockIdx.x * blockDim.x + threadIdx.x;
    if (i < DFEAT * DFEAT) {
        int k = i >> 7, n = i & 127;
        float w = W[i];                            // W[k][n]
        __nv_bfloat16 h = __float2bfloat16_rn(w);
        float lo = w - __bfloat162float(h);
        g_wh[n * DFEAT + k] = h;
        g_wl[n * DFEAT + k] = __float2bfloat16_rn(lo);
    }
}

// bf16x2 pack: low half = a, high half = b
__device__ __forceinline__ uint32_t pack_bf2(float a, float b) {
    uint32_t r;
    asm("cvt.rn.bf16x2.f32 %0, %1, %2;" : "=r"(r) : "f"(b), "f"(a));
    return r;
}

#define MMA(ac, a0, a1, a2, a3, b0, b1)                                      \
    asm volatile("mma.sync.aligned.m16n8k16.row.col.f32.bf16.bf16.f32 "      \
                 "{%0,%1,%2,%3}, {%4,%5,%6,%7}, {%8,%9}, {%0,%1,%2,%3};"     \
                 : "+f"(ac[0]), "+f"(ac[1]), "+f"(ac[2]), "+f"(ac[3])        \
                 : "r"(a0), "r"(a1), "r"(a2), "r"(a3), "r"(b0), "r"(b1))

// ---- GEMM: out[row] = (X[row] @ W) * dinv[row]  via mma.sync bf16x3 split ----
// CTA: 256 thr, 128 rows x 128 cols. Warp tile 32x64 (4 m-warps x 2 n-warps).
__global__ void __launch_bounds__(256, 2)
gemm_mma(const float* __restrict__ X, float* __restrict__ out, int nrows) {
    int lane = threadIdx.x & 31, wid = threadIdx.x >> 5;
    int gid = lane >> 2, tig = lane & 3;
    int wm = wid >> 1, wn = wid & 1;
    int row0 = blockIdx.x * 128 + wm * 32;   // warp's first row
    int n0w = wn * 64;                        // warp's first col

    float acc[2][8][4];
#pragma unroll
    for (int mt = 0; mt < 2; mt++)
#pragma unroll
        for (int nt = 0; nt < 8; nt++)
#pragma unroll
            for (int q = 0; q < 4; q++) acc[mt][nt][q] = 0.f;

#pragma unroll
    for (int ks = 0; ks < 8; ks++) {
        int kb = ks * 16;
        uint32_t ah[2][4], al[2][4];
        // A fragments (hi+lo) straight from global fp32 X
#pragma unroll
        for (int mt = 0; mt < 2; mt++) {
            int rbase = row0 + mt * 16 + gid;
#pragma unroll
            for (int q = 0; q < 4; q++) {
                int r = rbase + (q & 1) * 8;
                int c = kb + 2 * tig + (q >> 1) * 8;
                float2 v = make_float2(0.f, 0.f);
                if (r < nrows) v = *(const float2*)(X + (size_t)r * DFEAT + c);
                uint32_t h = pack_bf2(v.x, v.y);
                float hx = __uint_as_float(h << 16);
                float hy = __uint_as_float(h & 0xFFFF0000u);
                al[mt][q] = pack_bf2(v.x - hx, v.y - hy);
                ah[mt][q] = h;
            }
        }
        // per n8-tile: load B fragments (hi+lo), 3 MMAs per m-tile
#pragma unroll
        for (int nt = 0; nt < 8; nt++) {
            int nc = n0w + nt * 8 + gid;
            const uint32_t* ph = (const uint32_t*)(g_wh + nc * DFEAT + kb + 2 * tig);
            const uint32_t* pl = (const uint32_t*)(g_wl + nc * DFEAT + kb + 2 * tig);
            uint32_t bh0 = ph[0], bh1 = ph[4];   // +8 halves = +4 u32
            uint32_t bl0 = pl[0], bl1 = pl[4];
#pragma unroll
            for (int mt = 0; mt < 2; mt++) {
                MMA(acc[mt][nt], ah[mt][0], ah[mt][1], ah[mt][2], ah[mt][3], bh0, bh1);
                MMA(acc[mt][nt], ah[mt][0], ah[mt][1], ah[mt][2], ah[mt][3], bl0, bl1);
                MMA(acc[mt][nt], al[mt][0], al[mt][1], al[mt][2], al[mt][3], bh0, bh1);
            }
        }
    }

    // epilogue: *dinv, store
#pragma unroll
    for (int mt = 0; mt < 2; mt++) {
        int r = row0 + mt * 16 + gid;
        float d0 = (r < nrows) ? g_dinv[r] : 0.f;
        float d1 = (r + 8 < nrows) ? g_dinv[r + 8] : 0.f;
#pragma unroll
        for (int nt = 0; nt < 8; nt++) {
            int c = n0w + nt * 8 + 2 * tig;
            if (r < nrows)
                *(float2*)(out + (size_t)r * DFEAT + c) =
                    make_float2(acc[mt][nt][0] * d0, acc[mt][nt][1] * d0);
            if (r + 8 < nrows)
                *(float2*)(out + (size_t)(r + 8) * DFEAT + c) =
                    make_float2(acc[mt][nt][2] * d1, acc[mt][nt][3] * d1);
        }
    }
}

// ------ aggregation (round-2 verbatim) ------
__global__ void aggregate_relu(const float* __restrict__ hs,
                               const float* __restrict__ bias,
                               float* __restrict__ out) {
    int gw = (blockIdx.x * blockDim.x + threadIdx.x) >> 5;
    int lane = threadIdx.x & 31;
    if (gw >= N_NODES) return;
    const float4* hs4 = (const float4*)hs;
    float4 acc = hs4[(size_t)gw * 32 + lane];
    int e0 = g_rowptr[gw], e1 = g_rowptr[gw + 1];
    for (int e = e0; e < e1; e++) {
        int s = g_csr[e];
        float4 v = hs4[(size_t)s * 32 + lane];
        acc.x += v.x; acc.y += v.y; acc.z += v.z; acc.w += v.w;
    }
    float d = g_dinv[gw];
    float4 b = ((const float4*)bias)[lane];
    float4 r;
    r.x = fmaxf(fmaf(acc.x, d, b.x), 0.f);
    r.y = fmaxf(fmaf(acc.y, d, b.y), 0.f);
    r.z = fmaxf(fmaf(acc.z, d, b.z), 0.f);
    r.w = fmaxf(fmaf(acc.w, d, b.w), 0.f);
    ((float4*)out)[(size_t)gw * 32 + lane] = r;
}

__global__ void aggregate_final(const float* __restrict__ hs,
                                const float* __restrict__ bias,
                                const float* __restrict__ Wl,
                                const float* __restrict__ bl,
                                float* __restrict__ out) {
    int gw = (blockIdx.x * blockDim.x + threadIdx.x) >> 5;
    int lane = threadIdx.x & 31;
    if (gw >= N_NODES) return;
    const float4* hs4 = (const float4*)hs;
    float4 acc = hs4[(size_t)gw * 32 + lane];
    int e0 = g_rowptr[gw], e1 = g_rowptr[gw + 1];
    for (int e = e0; e < e1; e++) {
        int s = g_csr[e];
        float4 v = hs4[(size_t)s * 32 + lane];
        acc.x += v.x; acc.y += v.y; acc.z += v.z; acc.w += v.w;
    }
    float d = g_dinv[gw];
    float4 b = ((const float4*)bias)[lane];
    float4 r;
    r.x = fmaxf(fmaf(acc.x, d, b.x), 0.f);
    r.y = fmaxf(fmaf(acc.y, d, b.y), 0.f);
    r.z = fmaxf(fmaf(acc.z, d, b.z), 0.f);
    r.w = fmaxf(fmaf(acc.w, d, b.w), 0.f);
    float4 wl = ((const float4*)Wl)[lane];
    float dot = r.x * wl.x + r.y * wl.y + r.z * wl.z + r.w * wl.w;
#pragma unroll
    for (int off = 16; off; off >>= 1)
        dot += __shfl_xor_sync(0xFFFFFFFFu, dot, off);
    if (lane == 0) out[gw] = dot + bl[0];
}

// ---------------- launch ----------------
extern "C" void kernel_launch(void* const* d_in, const int* in_sizes, int n_in,
                              void* d_out, int out_size) {
    const float* x  = (const float*)d_in[0];
    const int*   ei = (const int*)d_in[1];    // int32 (JAX x64 disabled)
    const float* W1 = (const float*)d_in[2];
    const float* b1 = (const float*)d_in[3];
    const float* W2 = (const float*)d_in[4];
    const float* b2 = (const float*)d_in[5];
    const float* Wl = (const float*)d_in[6];
    const float* bl = (const float*)d_in[7];
    float* out = (float*)d_out;

    int E = in_sizes[1] / 2;
    const int* src = ei;
    const int* dst = ei + E;

    void *p_hs, *p_buf;
    cudaGetSymbolAddress(&p_hs, g_hs);
    cudaGetSymbolAddress(&p_buf, g_buf);
    float* hs  = (float*)p_hs;
    float* buf = (float*)p_buf;

    int gemm_grid = (N_NODES + 127) / 128;   // 391
    int agg_grid  = (N_NODES + 7) / 8;

    zero_counters<<<(N_NODES + 255) / 256, 256>>>();
    count_deg<<<(E + 255) / 256, 256>>>(dst, E);
    scan_deg<<<1, 1024>>>(E);
    fill_csr<<<(E + 255) / 256, 256>>>(src, dst, E);

    wconvert<<<(DFEAT * DFEAT + 255) / 256, 256>>>(W1);
    gemm_mma<<<gemm_grid, 256>>>(x, hs, N_NODES);
    aggregate_relu<<<agg_grid, 256>>>(hs, b1, buf);
    wconvert<<<(DFEAT * DFEAT + 255) / 256, 256>>>(W2);
    gemm_mma<<<gemm_grid, 256>>>(buf, hs, N_NODES);
    aggregate_final<<<agg_grid, 256>>>(hs, b2, Wl, bl, out);
}

// round 10
// speedup vs baseline: 1.2437x; 1.0169x over previous
#include <cuda_runtime.h>
#include <cuda_bf16.h>
#include <cstdint>

#define N_NODES 50000
#define DFEAT 128
#define MAX_E 800000

// ---- scratch (static device globals: allocation-free) ----
__device__ float g_hs[N_NODES * DFEAT];    // (X@W) * dinv[row]
__device__ float g_buf[N_NODES * DFEAT];   // layer-1 output / layer-2 input
__device__ float g_dinv[N_NODES];
__device__ int   g_cnt[N_NODES];
__device__ int   g_cursor[N_NODES];
__device__ int   g_rowptr[N_NODES + 1];
__device__ int   g_csr[MAX_E];
__device__ __nv_bfloat16 g_wh[DFEAT * DFEAT];    // W1^T hi  [n][k]
__device__ __nv_bfloat16 g_wl[DFEAT * DFEAT];    // W1^T lo
__device__ __nv_bfloat16 g_wh2[DFEAT * DFEAT];   // W2^T hi
__device__ __nv_bfloat16 g_wl2[DFEAT * DFEAT];   // W2^T lo

// ---------------- graph build (round-2 verbatim) ----------------
__global__ void zero_counters() {
    int i = blockIdx.x * blockDim.x + threadIdx.x;
    if (i < N_NODES) { g_cnt[i] = 0; g_cursor[i] = 0; }
}
__global__ void count_deg(const int* __restrict__ dst, int E) {
    int e = blockIdx.x * blockDim.x + threadIdx.x;
    if (e < E) atomicAdd(&g_cnt[dst[e]], 1);
}
__global__ void scan_deg(int E) {
    __shared__ int part[1024];
    int t = threadIdx.x;
    const int C = (N_NODES + 1023) / 1024;
    int lo = t * C, hi = min(lo + C, N_NODES);
    int s = 0;
    for (int i = lo; i < hi; i++) s += g_cnt[i];
    part[t] = s;
    __syncthreads();
    for (int off = 1; off < 1024; off <<= 1) {
        int v = (t >= off) ? part[t - off] : 0;
        __syncthreads();
        part[t] += v;
        __syncthreads();
    }
    int run = (t > 0) ? part[t - 1] : 0;
    for (int i = lo; i < hi; i++) {
        g_rowptr[i] = run;
        int c = g_cnt[i];
        run += c;
        g_dinv[i] = rsqrtf((float)c + 1.0f);
    }
    if (t == 0) g_rowptr[N_NODES] = E;
}
__global__ void fill_csr(const int* __restrict__ src,
                         const int* __restrict__ dst, int E) {
    int e = blockIdx.x * blockDim.x + threadIdx.x;
    if (e < E) {
        int d = dst[e];
        int pos = atomicAdd(&g_cursor[d], 1);
        g_csr[g_rowptr[d] + pos] = src[e];
    }
}

// ---------------- W -> transposed bf16 hi/lo ----------------
__global__ void wconvert(const float* __restrict__ W,
                         __nv_bfloat16* __restrict__ wh,
                         __nv_bfloat16* __restrict__ wl) {
    int i = blockIdx.x * blockDim.x + threadIdx.x;
    if (i < DFEAT * DFEAT) {
        int k = i >> 7, n = i & 127;
        float w = W[i];                            // W[k][n]
        __nv_bfloat16 h = __float2bfloat16_rn(w);
        float lo = w - __bfloat162float(h);
        wh[n * DFEAT + k] = h;
        wl[n * DFEAT + k] = __float2bfloat16_rn(lo);
    }
}

// bf16x2 pack: low half = a, high half = b
__device__ __forceinline__ uint32_t pack_bf2(float a, float b) {
    uint32_t r;
    asm("cvt.rn.bf16x2.f32 %0, %1, %2;" : "=r"(r) : "f"(b), "f"(a));
    return r;
}

#define MMA(ac, a0, a1, a2, a3, b0, b1)                                      \
    asm volatile("mma.sync.aligned.m16n8k16.row.col.f32.bf16.bf16.f32 "      \
                 "{%0,%1,%2,%3}, {%4,%5,%6,%7}, {%8,%9}, {%0,%1,%2,%3};"     \
                 : "+f"(ac[0]), "+f"(ac[1]), "+f"(ac[2]), "+f"(ac[3])        \
                 : "r"(a0), "r"(a1), "r"(a2), "r"(a3), "r"(b0), "r"(b1))

// ---- GEMM: out[row] = (X[row] @ W) * dinv[row]  via mma.sync bf16x3 split ----
// CTA: 256 thr, 128 rows x 128 cols. Warp tile 32x64 (4 m-warps x 2 n-warps).
__global__ void __launch_bounds__(256, 2)
gemm_mma(const float* __restrict__ X,
         const __nv_bfloat16* __restrict__ wh,
         const __nv_bfloat16* __restrict__ wl,
         float* __restrict__ out, int nrows) {
    int lane = threadIdx.x & 31, wid = threadIdx.x >> 5;
    int gid = lane >> 2, tig = lane & 3;
    int wm = wid >> 1, wn = wid & 1;
    int row0 = blockIdx.x * 128 + wm * 32;   // warp's first row
    int n0w = wn * 64;                        // warp's first col

    float acc[2][8][4];
#pragma unroll
    for (int mt = 0; mt < 2; mt++)
#pragma unroll
        for (int nt = 0; nt < 8; nt++)
#pragma unroll
            for (int q = 0; q < 4; q++) acc[mt][nt][q] = 0.f;

#pragma unroll
    for (int ks = 0; ks < 8; ks++) {
        int kb = ks * 16;
        uint32_t ah[2][4], al[2][4];
        // A fragments (hi+lo) straight from global fp32 X
#pragma unroll
        for (int mt = 0; mt < 2; mt++) {
            int rbase = row0 + mt * 16 + gid;
#pragma unroll
            for (int q = 0; q < 4; q++) {
                int r = rbase + (q & 1) * 8;
                int c = kb + 2 * tig + (q >> 1) * 8;
                float2 v = make_float2(0.f, 0.f);
                if (r < nrows) v = *(const float2*)(X + (size_t)r * DFEAT + c);
                uint32_t h = pack_bf2(v.x, v.y);
                float hx = __uint_as_float(h << 16);
                float hy = __uint_as_float(h & 0xFFFF0000u);
                al[mt][q] = pack_bf2(v.x - hx, v.y - hy);
                ah[mt][q] = h;
            }
        }
        // per n8-tile: load B fragments (hi+lo), 3 MMAs per m-tile
#pragma unroll
        for (int nt = 0; nt < 8; nt++) {
            int nc = n0w + nt * 8 + gid;
            const uint32_t* ph = (const uint32_t*)(wh + nc * DFEAT + kb + 2 * tig);
            const uint32_t* pl = (const uint32_t*)(wl + nc * DFEAT + kb + 2 * tig);
            uint32_t bh0 = ph[0], bh1 = ph[4];   // +8 halves = +4 u32
            uint32_t bl0 = pl[0], bl1 = pl[4];
#pragma unroll
            for (int mt = 0; mt < 2; mt++) {
                MMA(acc[mt][nt], ah[mt][0], ah[mt][1], ah[mt][2], ah[mt][3], bh0, bh1);
                MMA(acc[mt][nt], ah[mt][0], ah[mt][1], ah[mt][2], ah[mt][3], bl0, bl1);
                MMA(acc[mt][nt], al[mt][0], al[mt][1], al[mt][2], al[mt][3], bh0, bh1);
            }
        }
    }

    // epilogue: *dinv, store
#pragma unroll
    for (int mt = 0; mt < 2; mt++) {
        int r = row0 + mt * 16 + gid;
        float d0 = (r < nrows) ? g_dinv[r] : 0.f;
        float d1 = (r + 8 < nrows) ? g_dinv[r + 8] : 0.f;
#pragma unroll
        for (int nt = 0; nt < 8; nt++) {
            int c = n0w + nt * 8 + 2 * tig;
            if (r < nrows)
                *(float2*)(out + (size_t)r * DFEAT + c) =
                    make_float2(acc[mt][nt][0] * d0, acc[mt][nt][1] * d0);
            if (r + 8 < nrows)
                *(float2*)(out + (size_t)(r + 8) * DFEAT + c) =
                    make_float2(acc[mt][nt][2] * d1, acc[mt][nt][3] * d1);
        }
    }
}

// ------ aggregation (round-2 verbatim) ------
__global__ void aggregate_relu(const float* __restrict__ hs,
                               const float* __restrict__ bias,
                               float* __restrict__ out) {
    int gw = (blockIdx.x * blockDim.x + threadIdx.x) >> 5;
    int lane = threadIdx.x & 31;
    if (gw >= N_NODES) return;
    const float4* hs4 = (const float4*)hs;
    float4 acc = hs4[(size_t)gw * 32 + lane];
    int e0 = g_rowptr[gw], e1 = g_rowptr[gw + 1];
    for (int e = e0; e < e1; e++) {
        int s = g_csr[e];
        float4 v = hs4[(size_t)s * 32 + lane];
        acc.x += v.x; acc.y += v.y; acc.z += v.z; acc.w += v.w;
    }
    float d = g_dinv[gw];
    float4 b = ((const float4*)bias)[lane];
    float4 r;
    r.x = fmaxf(fmaf(acc.x, d, b.x), 0.f);
    r.y = fmaxf(fmaf(acc.y, d, b.y), 0.f);
    r.z = fmaxf(fmaf(acc.z, d, b.z), 0.f);
    r.w = fmaxf(fmaf(acc.w, d, b.w), 0.f);
    ((float4*)out)[(size_t)gw * 32 + lane] = r;
}

__global__ void aggregate_final(const float* __restrict__ hs,
                                const float* __restrict__ bias,
                                const float* __restrict__ Wl,
                                const float* __restrict__ bl,
                                float* __restrict__ out) {
    int gw = (blockIdx.x * blockDim.x + threadIdx.x) >> 5;
    int lane = threadIdx.x & 31;
    if (gw >= N_NODES) return;
    const float4* hs4 = (const float4*)hs;
    float4 acc = hs4[(size_t)gw * 32 + lane];
    int e0 = g_rowptr[gw], e1 = g_rowptr[gw + 1];
    for (int e = e0; e < e1; e++) {
        int s = g_csr[e];
        float4 v = hs4[(size_t)s * 32 + lane];
        acc.x += v.x; acc.y += v.y; acc.z += v.z; acc.w += v.w;
    }
    float d = g_dinv[gw];
    float4 b = ((const float4*)bias)[lane];
    float4 r;
    r.x = fmaxf(fmaf(acc.x, d, b.x), 0.f);
    r.y = fmaxf(fmaf(acc.y, d, b.y), 0.f);
    r.z = fmaxf(fmaf(acc.z, d, b.z), 0.f);
    r.w = fmaxf(fmaf(acc.w, d, b.w), 0.f);
    float4 wl = ((const float4*)Wl)[lane];
    float dot = r.x * wl.x + r.y * wl.y + r.z * wl.z + r.w * wl.w;
#pragma unroll
    for (int off = 16; off; off >>= 1)
        dot += __shfl_xor_sync(0xFFFFFFFFu, dot, off);
    if (lane == 0) out[gw] = dot + bl[0];
}

// ---------------- launch ----------------
extern "C" void kernel_launch(void* const* d_in, const int* in_sizes, int n_in,
                              void* d_out, int out_size) {
    const float* x  = (const float*)d_in[0];
    const int*   ei = (const int*)d_in[1];    // int32 (JAX x64 disabled)
    const float* W1 = (const float*)d_in[2];
    const float* b1 = (const float*)d_in[3];
    const float* W2 = (const float*)d_in[4];
    const float* b2 = (const float*)d_in[5];
    const float* Wl = (const float*)d_in[6];
    const float* bl = (const float*)d_in[7];
    float* out = (float*)d_out;

    int E = in_sizes[1] / 2;
    const int* src = ei;
    const int* dst = ei + E;

    void *p_hs, *p_buf, *p_wh, *p_wl, *p_wh2, *p_wl2;
    cudaGetSymbolAddress(&p_hs, g_hs);
    cudaGetSymbolAddress(&p_buf, g_buf);
    cudaGetSymbolAddress(&p_wh, g_wh);
    cudaGetSymbolAddress(&p_wl, g_wl);
    cudaGetSymbolAddress(&p_wh2, g_wh2);
    cudaGetSymbolAddress(&p_wl2, g_wl2);
    float* hs  = (float*)p_hs;
    float* buf = (float*)p_buf;
    __nv_bfloat16* wh  = (__nv_bfloat16*)p_wh;
    __nv_bfloat16* wl  = (__nv_bfloat16*)p_wl;
    __nv_bfloat16* wh2 = (__nv_bfloat16*)p_wh2;
    __nv_bfloat16* wl2 = (__nv_bfloat16*)p_wl2;

    static cudaStream_t s2 = []() {
        cudaStream_t s; cudaStreamCreateWithFlags(&s, cudaStreamNonBlocking); return s;
    }();
    static cudaEvent_t evF = []() {
        cudaEvent_t e; cudaEventCreateWithFlags(&e, cudaEventDisableTiming); return e;
    }();
    static cudaEvent_t evJ = []() {
        cudaEvent_t e; cudaEventCreateWithFlags(&e, cudaEventDisableTiming); return e;
    }();

    int gemm_grid = (N_NODES + 127) / 128;   // 391
    int agg_grid  = (N_NODES + 7) / 8;
    int wcv_grid  = (DFEAT * DFEAT + 255) / 256;

    // serial prefix: gemm1 needs scan_deg (dinv) + wconvert(W1)
    zero_counters<<<(N_NODES + 255) / 256, 256>>>();
    count_deg<<<(E + 255) / 256, 256>>>(dst, E);
    scan_deg<<<1, 1024>>>(E);
    wconvert<<<wcv_grid, 256>>>(W1, wh, wl);

    // fork: fill_csr + wconvert(W2) on s2  ||  gemm1 on main
    cudaEventRecord(evF, 0);
    cudaStreamWaitEvent(s2, evF, 0);
    fill_csr<<<(E + 255) / 256, 256, 0, s2>>>(src, dst, E);
    wconvert<<<wcv_grid, 256, 0, s2>>>(W2, wh2, wl2);
    cudaEventRecord(evJ, s2);

    gemm_mma<<<gemm_grid, 256>>>(x, wh, wl, hs, N_NODES);

    // join: agg1 needs the CSR
    cudaStreamWaitEvent(0, evJ, 0);
    aggregate_relu<<<agg_grid, 256>>>(hs, b1, buf);
    gemm_mma<<<gemm_grid, 256>>>(buf, wh2, wl2, hs, N_NODES);
    aggregate_final<<<agg_grid, 256>>>(hs, b2, Wl, bl, out);
}